// round 3
// baseline (speedup 1.0000x reference)
#include <cuda_runtime.h>
#include <cuda_bf16.h>
#include <cstdint>

// Problem constants (fixed by the reference)
#define NB 32      // batch
#define NZ 4000    // nodes
#define NIN 32     // in features
#define NH 64      // hidden
#define NE 64000   // edges

// Scratch (device globals; no allocations allowed)
__device__ float  g_y[NZ * NB];      // y[z*NB + b] = x[b,z,:] . v
__device__ int    g_deg[NZ];         // in-degree (EXCLUDING self-loop)
__device__ int    g_rowptr[NZ + 1];  // CSR row offsets (by dst)
__device__ int    g_cursor[NZ];      // fill cursors
__device__ float2 g_csr[NE];         // per edge: (.x = src as int bits, .y = norm)
__device__ float  g_v[NIN];          // W @ fc_W
__device__ float  g_const;           // b . fc_W + fc_b

// ---------------------------------------------------------------------------
// K1: zero deg; block 0 also computes v = W@fc_W and the scalar const.
// ---------------------------------------------------------------------------
__global__ void k_init(const float* __restrict__ W,
                       const float* __restrict__ bias,
                       const float* __restrict__ fcW,
                       const float* __restrict__ fcb) {
    int t = blockIdx.x * blockDim.x + threadIdx.x;
    if (t < NZ) g_deg[t] = 0;
    if (blockIdx.x == 0) {
        if (threadIdx.x < NIN) {
            float s = 0.f;
            #pragma unroll
            for (int h = 0; h < NH; ++h) s += W[threadIdx.x * NH + h] * fcW[h];
            g_v[threadIdx.x] = s;
        } else if (threadIdx.x == NIN) {
            float s = fcb[0];
            #pragma unroll
            for (int h = 0; h < NH; ++h) s += bias[h] * fcW[h];
            g_const = s;
        }
    }
}

// ---------------------------------------------------------------------------
// K2: in-degree histogram over edge destinations (self-loops excluded;
//     all consumers use deg+1).
// ---------------------------------------------------------------------------
__global__ void k_deg(const int* __restrict__ dst) {
    int e = blockIdx.x * blockDim.x + threadIdx.x;
    if (e < NE) atomicAdd(&g_deg[dst[e]], 1);
}

// ---------------------------------------------------------------------------
// K3: fused ydot + degree scan.
// Blocks [0, NYB): coalesced y-dot. Thread t loads float4 #t of x (flat),
//   lanes 8k..8k+7 cover one (b,z) row; 3-step xor-shuffle reduce; leader
//   writes y[z*NB+b].
// Block NYB (last): exclusive scan of g_deg[0..NZ) -> g_rowptr / g_cursor.
// ---------------------------------------------------------------------------
#define NYB ((NB * NZ * (NIN / 4)) / 256)   // 4000 ydot blocks

__global__ void k_ydot_scan(const float* __restrict__ x) {
    if (blockIdx.x < NYB) {
        int t = blockIdx.x * blockDim.x + threadIdx.x;   // < NB*NZ*NIN/4
        float4 xv = reinterpret_cast<const float4*>(x)[t];
        float4 vv = reinterpret_cast<const float4*>(g_v)[t & 7];
        float p = xv.x * vv.x + xv.y * vv.y + xv.z * vv.z + xv.w * vv.w;
        p += __shfl_xor_sync(0xFFFFFFFFu, p, 1);
        p += __shfl_xor_sync(0xFFFFFFFFu, p, 2);
        p += __shfl_xor_sync(0xFFFFFFFFu, p, 4);
        if ((t & 7) == 0) {
            int f = t >> 3;             // row index = b*NZ + z
            int b = f / NZ;
            int z = f - b * NZ;
            g_y[z * NB + b] = p;
        }
        return;
    }
    // ---- scan block: 256 threads, chunk of 16 nodes each (256*16 = 4096) ----
    __shared__ int warp_sums[8];
    const int CH = 16;
    int t    = threadIdx.x;
    int lane = t & 31;
    int wid  = t >> 5;
    int base = t * CH;

    int local[CH];
    int s = 0;
    #pragma unroll
    for (int j = 0; j < CH; ++j) {
        int z = base + j;
        int d = (z < NZ) ? g_deg[z] : 0;
        local[j] = s;          // exclusive within chunk
        s += d;
    }
    // inclusive warp scan of chunk sums
    int v = s;
    #pragma unroll
    for (int o = 1; o < 32; o <<= 1) {
        int n = __shfl_up_sync(0xFFFFFFFFu, v, o);
        if (lane >= o) v += n;
    }
    if (lane == 31) warp_sums[wid] = v;
    __syncthreads();
    if (wid == 0) {
        int wv = (lane < 8) ? warp_sums[lane] : 0;
        #pragma unroll
        for (int o = 1; o < 8; o <<= 1) {
            int n = __shfl_up_sync(0xFFFFFFFFu, wv, o);
            if (lane >= o) wv += n;
        }
        if (lane < 8) warp_sums[lane] = wv;   // inclusive warp sums
    }
    __syncthreads();
    int thread_excl = (v - s) + (wid > 0 ? warp_sums[wid - 1] : 0);
    #pragma unroll
    for (int j = 0; j < CH; ++j) {
        int z = base + j;
        if (z < NZ) {
            int off = thread_excl + local[j];
            g_rowptr[z] = off;
            g_cursor[z] = off;
        }
    }
    if (t == 0) g_rowptr[NZ] = NE;
}

// ---------------------------------------------------------------------------
// K4: fill CSR. Per edge: slot via cursor atomic; store (src, norm) packed.
// norm = rsqrt((deg[s]+1)*(deg[d]+1))  (deg+1 == PyG degree incl. self-loop)
// ---------------------------------------------------------------------------
__global__ void k_fill(const int* __restrict__ src,
                       const int* __restrict__ dst) {
    int e = blockIdx.x * blockDim.x + threadIdx.x;
    if (e >= NE) return;
    int s = src[e];
    int d = dst[e];
    float w = rsqrtf((float)((g_deg[s] + 1) * (g_deg[d] + 1)));
    int slot = atomicAdd(&g_cursor[d], 1);
    g_csr[slot] = make_float2(__int_as_float(s), w);
}

// ---------------------------------------------------------------------------
// K5: gather + self-loop + transposed store. Warp per dst node, lane per b.
// No atomics; 4-wide unrolled independent L2 loads for MLP.
// ---------------------------------------------------------------------------
__global__ void k_gather(float* __restrict__ out) {
    int gt   = blockIdx.x * blockDim.x + threadIdx.x;
    int z    = gt >> 5;                 // warp id = dst node
    int lane = gt & 31;                 // batch index
    if (z >= NZ) return;

    int beg = g_rowptr[z];
    int end = g_rowptr[z + 1];

    float val = 0.f;
    int i = beg;
    for (; i + 4 <= end; i += 4) {
        float2 e0 = g_csr[i + 0];
        float2 e1 = g_csr[i + 1];
        float2 e2 = g_csr[i + 2];
        float2 e3 = g_csr[i + 3];
        float y0 = g_y[__float_as_int(e0.x) * NB + lane];
        float y1 = g_y[__float_as_int(e1.x) * NB + lane];
        float y2 = g_y[__float_as_int(e2.x) * NB + lane];
        float y3 = g_y[__float_as_int(e3.x) * NB + lane];
        val += e0.y * y0 + e1.y * y1 + e2.y * y2 + e3.y * y3;
    }
    for (; i < end; ++i) {
        float2 e = g_csr[i];
        val += e.y * g_y[__float_as_int(e.x) * NB + lane];
    }
    // self-loop: dinv^2 * y = y / (deg+1)
    float dz = rsqrtf((float)(g_deg[z] + 1));
    val += dz * dz * g_y[z * NB + lane];

    out[(size_t)lane * NZ + z] = val + g_const;
}

// ---------------------------------------------------------------------------
extern "C" void kernel_launch(void* const* d_in, const int* in_sizes, int n_in,
                              void* d_out, int out_size) {
    const float* x    = (const float*)d_in[0];   // [32,4000,32]
    const int*   ei   = (const int*)  d_in[1];   // [2,64000]
    const float* W    = (const float*)d_in[2];   // [32,64]
    const float* bias = (const float*)d_in[3];   // [64]
    const float* fcW  = (const float*)d_in[4];   // [64]
    const float* fcb  = (const float*)d_in[5];   // [1]
    float* out = (float*)d_out;                  // [32,4000]

    const int* src = ei;
    const int* dst = ei + NE;

    k_init<<<(NZ + 255) / 256, 256>>>(W, bias, fcW, fcb);
    k_deg<<<(NE + 255) / 256, 256>>>(dst);
    k_ydot_scan<<<NYB + 1, 256>>>(x);
    k_fill<<<(NE + 255) / 256, 256>>>(src, dst);
    k_gather<<<(NZ * 32 + 255) / 256, 256>>>(out);
}